// round 1
// baseline (speedup 1.0000x reference)
#include <cuda_runtime.h>
#include <math.h>

#define Bb 2
#define Ss 2048
#define Ee 2048
#define NH 16
#define NKV 4
#define HD 128
#define WIN 1024
#define GQ (NH / NKV)

// Scratch (device globals; no allocation allowed)
__device__ float g_q[(size_t)Bb * Ss * NH * HD];    // 33.5 MB
__device__ float g_k[(size_t)Bb * Ss * NKV * HD];   //  8.4 MB
__device__ float g_v[(size_t)Bb * Ss * NKV * HD];   //  8.4 MB
__device__ float g_ao[(size_t)Bb * Ss * NH * HD];   // 33.5 MB

// ---------------------------------------------------------------------------
// SGEMM (NT): C[M,N] = A[M,K] @ B[N,K]^T. All row-major. M%128==0, N%128==0,
// K%16==0. 128x128 tile, BK=16, 256 threads, 8x8 per-thread micro-tile.
// ---------------------------------------------------------------------------
#define ASL 132  // padded k-major stride (132*4B = 528B, 16B aligned)

__global__ void __launch_bounds__(256) sgemm_nt(
    const float* __restrict__ A, const float* __restrict__ Bm,
    float* __restrict__ C, int M, int N, int K)
{
    __shared__ float As[16 * ASL];
    __shared__ float Bs[16 * ASL];

    const int t  = threadIdx.x;
    const int bm = blockIdx.y, bn = blockIdx.x;
    const int tx = t & 15, ty = t >> 4;

    const float* Ab = A  + (size_t)bm * 128 * K;
    const float* Bt = Bm + (size_t)bn * 128 * K;

    float acc[8][8];
#pragma unroll
    for (int i = 0; i < 8; i++)
#pragma unroll
        for (int j = 0; j < 8; j++) acc[i][j] = 0.f;

    for (int kt = 0; kt < K; kt += 16) {
#pragma unroll
        for (int r = 0; r < 2; r++) {
            int lin = t + r * 256;          // 0..511 float4 slots (= 2048 floats)
            int row = lin >> 2;             // 0..127
            int c4  = lin & 3;              // 0..3
            float4 va = *(const float4*)(Ab + (size_t)row * K + kt + c4 * 4);
            As[(c4 * 4 + 0) * ASL + row] = va.x;
            As[(c4 * 4 + 1) * ASL + row] = va.y;
            As[(c4 * 4 + 2) * ASL + row] = va.z;
            As[(c4 * 4 + 3) * ASL + row] = va.w;
            float4 vb = *(const float4*)(Bt + (size_t)row * K + kt + c4 * 4);
            Bs[(c4 * 4 + 0) * ASL + row] = vb.x;
            Bs[(c4 * 4 + 1) * ASL + row] = vb.y;
            Bs[(c4 * 4 + 2) * ASL + row] = vb.z;
            Bs[(c4 * 4 + 3) * ASL + row] = vb.w;
        }
        __syncthreads();

#pragma unroll
        for (int k = 0; k < 16; k++) {
            float4 a0 = *(const float4*)(As + k * ASL + ty * 8);
            float4 a1 = *(const float4*)(As + k * ASL + ty * 8 + 4);
            float4 b0 = *(const float4*)(Bs + k * ASL + tx * 8);
            float4 b1 = *(const float4*)(Bs + k * ASL + tx * 8 + 4);
            float a[8] = {a0.x, a0.y, a0.z, a0.w, a1.x, a1.y, a1.z, a1.w};
            float b[8] = {b0.x, b0.y, b0.z, b0.w, b1.x, b1.y, b1.z, b1.w};
#pragma unroll
            for (int i = 0; i < 8; i++)
#pragma unroll
                for (int j = 0; j < 8; j++) acc[i][j] += a[i] * b[j];
        }
        __syncthreads();
    }

#pragma unroll
    for (int i = 0; i < 8; i++) {
        float* cp = C + (size_t)(bm * 128 + ty * 8 + i) * N + bn * 128 + tx * 8;
        *(float4*)(cp)     = make_float4(acc[i][0], acc[i][1], acc[i][2], acc[i][3]);
        *(float4*)(cp + 4) = make_float4(acc[i][4], acc[i][5], acc[i][6], acc[i][7]);
    }
}

// ---------------------------------------------------------------------------
// RoPE (duplicated-half layout). data: [B, S, nheads, HD].
// Each thread handles one (d, d+64) pair.
// ---------------------------------------------------------------------------
__global__ void rope_kernel(float* __restrict__ data,
                            const float* __restrict__ cosT,
                            const float* __restrict__ sinT, int nheads, int total)
{
    int i = blockIdx.x * blockDim.x + threadIdx.x;
    if (i >= total) return;
    int d    = i & 63;
    int rest = i >> 6;
    int h    = rest % nheads;
    int bs   = rest / nheads;     // b*S + s
    int s    = bs & (Ss - 1);
    size_t base = ((size_t)bs * nheads + h) * HD;
    float x1 = data[base + d];
    float x2 = data[base + d + 64];
    float c1 = cosT[s * HD + d],      s1 = sinT[s * HD + d];
    float c2 = cosT[s * HD + d + 64], s2 = sinT[s * HD + d + 64];
    data[base + d]      = x1 * c1 - x2 * s1;
    data[base + d + 64] = x2 * c2 + x1 * s2;
}

// ---------------------------------------------------------------------------
// Windowed-causal flash attention, fp32.
// CTA: 64 queries x one head x one batch. 256 threads.
// Score micro-tile 4x4 (16x16 thread grid); PV micro-tile 4 rows x 8 cols.
// smem: Qs[64][132] | KVs[64][132] (K then reused for V) | Ps[64][68]
// ---------------------------------------------------------------------------
#define QLD 132
#define PLD 68
#define FLASH_SMEM ((2 * 64 * QLD + 64 * PLD) * 4)  // 84992 B

__global__ void __launch_bounds__(256, 2) flash_kernel(
    const float* __restrict__ gq, const float* __restrict__ gk,
    const float* __restrict__ gv, float* __restrict__ gao)
{
    extern __shared__ float sm[];
    float* Qs  = sm;
    float* KVs = sm + 64 * QLD;
    float* Ps  = sm + 2 * 64 * QLD;

    const int t  = threadIdx.x;
    const int qt = blockIdx.x, h = blockIdx.y, b = blockIdx.z;
    const int hk = h / GQ;
    const int q0 = qt * 64;
    const int tx = t & 15, ty = t >> 4;
    const float scale = 0.08838834764831845f;  // 1/sqrt(128)

    // Load+scale Q tile (fully coalesced: one warp = one 512B row)
#pragma unroll
    for (int r = 0; r < 8; r++) {
        int lin = t + r * 256;            // 0..2047 float4 slots
        int row = lin >> 5, c4 = lin & 31;
        float4 v = *(const float4*)(gq + (((size_t)(b * Ss + q0 + row)) * NH + h) * HD + c4 * 4);
        v.x *= scale; v.y *= scale; v.z *= scale; v.w *= scale;
        *(float4*)(Qs + row * QLD + c4 * 4) = v;
    }

    float m[4], l[4], o[4][8];
#pragma unroll
    for (int i = 0; i < 4; i++) {
        m[i] = -1e30f; l[i] = 0.f;
#pragma unroll
        for (int c = 0; c < 8; c++) o[i][c] = 0.f;
    }

    int jstart = q0 - (WIN - 1); if (jstart < 0) jstart = 0;
    const int jt0 = jstart >> 6;
    const int jt1 = qt;

    for (int jt = jt0; jt <= jt1; jt++) {
        const int j0 = jt * 64;
        __syncthreads();  // prev iteration's PV reads of KVs done; Q visible on iter 1
        // Load K tile
#pragma unroll
        for (int r = 0; r < 8; r++) {
            int lin = t + r * 256;
            int row = lin >> 5, c4 = lin & 31;
            *(float4*)(KVs + row * QLD + c4 * 4) =
                *(const float4*)(gk + (((size_t)(b * Ss + j0 + row)) * NKV + hk) * HD + c4 * 4);
        }
        __syncthreads();

        // Scores: S[4][4] = Q rows (ty*4..+3) x K rows (tx*4..+3)
        float s[4][4];
#pragma unroll
        for (int i = 0; i < 4; i++)
#pragma unroll
            for (int j = 0; j < 4; j++) s[i][j] = 0.f;

#pragma unroll 4
        for (int kk = 0; kk < HD; kk += 4) {
            float4 qf[4], kf[4];
#pragma unroll
            for (int i = 0; i < 4; i++) qf[i] = *(const float4*)(Qs + (ty * 4 + i) * QLD + kk);
#pragma unroll
            for (int j = 0; j < 4; j++) kf[j] = *(const float4*)(KVs + (tx * 4 + j) * QLD + kk);
#pragma unroll
            for (int i = 0; i < 4; i++)
#pragma unroll
                for (int j = 0; j < 4; j++)
                    s[i][j] += qf[i].x * kf[j].x + qf[i].y * kf[j].y
                             + qf[i].z * kf[j].z + qf[i].w * kf[j].w;
        }

        // Mask + online softmax
        float mn[4];
#pragma unroll
        for (int i = 0; i < 4; i++) {
            int gi = q0 + ty * 4 + i;
            float rm = m[i];
#pragma unroll
            for (int j = 0; j < 4; j++) {
                int dist = gi - (j0 + tx * 4 + j);
                if (dist < 0 || dist >= WIN) s[i][j] = -1e30f;
                rm = fmaxf(rm, s[i][j]);
            }
            mn[i] = rm;
        }
#pragma unroll
        for (int i = 0; i < 4; i++)
#pragma unroll
            for (int off = 8; off; off >>= 1)
                mn[i] = fmaxf(mn[i], __shfl_xor_sync(0xffffffffu, mn[i], off));

#pragma unroll
        for (int i = 0; i < 4; i++) {
            float alpha = __expf(m[i] - mn[i]);
            l[i] *= alpha;
#pragma unroll
            for (int c = 0; c < 8; c++) o[i][c] *= alpha;
            float rs = 0.f;
#pragma unroll
            for (int j = 0; j < 4; j++) {
                float p = (s[i][j] > -1e29f) ? __expf(s[i][j] - mn[i]) : 0.f;
                s[i][j] = p;
                rs += p;
            }
#pragma unroll
            for (int off = 8; off; off >>= 1)
                rs += __shfl_xor_sync(0xffffffffu, rs, off);
            l[i] += rs;
            m[i] = mn[i];
        }

        // Store P (row-major, float4, conflict-free)
#pragma unroll
        for (int i = 0; i < 4; i++)
            *(float4*)(Ps + (ty * 4 + i) * PLD + tx * 4) =
                make_float4(s[i][0], s[i][1], s[i][2], s[i][3]);
        __syncthreads();  // scores done reading KVs; P visible

        // Load V tile into KVs
#pragma unroll
        for (int r = 0; r < 8; r++) {
            int lin = t + r * 256;
            int row = lin >> 5, c4 = lin & 31;
            *(float4*)(KVs + row * QLD + c4 * 4) =
                *(const float4*)(gv + (((size_t)(b * Ss + j0 + row)) * NKV + hk) * HD + c4 * 4);
        }
        __syncthreads();

        // O[rows ty*4..+3][cols tx*8..+7] += P @ V
#pragma unroll 4
        for (int j = 0; j < 64; j++) {
            float4 v0 = *(const float4*)(KVs + j * QLD + tx * 8);
            float4 v1 = *(const float4*)(KVs + j * QLD + tx * 8 + 4);
#pragma unroll
            for (int i = 0; i < 4; i++) {
                float p = Ps[(ty * 4 + i) * PLD + j];
                o[i][0] += p * v0.x; o[i][1] += p * v0.y;
                o[i][2] += p * v0.z; o[i][3] += p * v0.w;
                o[i][4] += p * v1.x; o[i][5] += p * v1.y;
                o[i][6] += p * v1.z; o[i][7] += p * v1.w;
            }
        }
    }

    // Epilogue: normalize + write
#pragma unroll
    for (int i = 0; i < 4; i++) {
        float inv = 1.f / l[i];
        float* op = gao + (((size_t)(b * Ss + q0 + ty * 4 + i)) * NH + h) * HD + tx * 8;
        *(float4*)(op)     = make_float4(o[i][0] * inv, o[i][1] * inv, o[i][2] * inv, o[i][3] * inv);
        *(float4*)(op + 4) = make_float4(o[i][4] * inv, o[i][5] * inv, o[i][6] * inv, o[i][7] * inv);
    }
}

// ---------------------------------------------------------------------------
extern "C" void kernel_launch(void* const* d_in, const int* in_sizes, int n_in,
                              void* d_out, int out_size)
{
    const float* x    = (const float*)d_in[0];
    const float* cosT = (const float*)d_in[1];
    const float* sinT = (const float*)d_in[2];
    const float* Wq   = (const float*)d_in[3];
    const float* Wk   = (const float*)d_in[4];
    const float* Wv   = (const float*)d_in[5];
    const float* Wo   = (const float*)d_in[6];
    float* out = (float*)d_out;

    void *pq, *pk, *pv, *pao;
    cudaGetSymbolAddress(&pq,  g_q);
    cudaGetSymbolAddress(&pk,  g_k);
    cudaGetSymbolAddress(&pv,  g_v);
    cudaGetSymbolAddress(&pao, g_ao);
    float* q  = (float*)pq;
    float* k  = (float*)pk;
    float* v  = (float*)pv;
    float* ao = (float*)pao;

    const int M = Bb * Ss;  // 4096

    // QKV projections
    sgemm_nt<<<dim3(Ee / 128, M / 128), 256>>>(x, Wq, q, M, NH * HD, Ee);
    sgemm_nt<<<dim3((NKV * HD) / 128, M / 128), 256>>>(x, Wk, k, M, NKV * HD, Ee);
    sgemm_nt<<<dim3((NKV * HD) / 128, M / 128), 256>>>(x, Wv, v, M, NKV * HD, Ee);

    // RoPE on q and k
    {
        int tq = Bb * Ss * NH * 64;
        rope_kernel<<<(tq + 255) / 256, 256>>>(q, cosT, sinT, NH, tq);
        int tk = Bb * Ss * NKV * 64;
        rope_kernel<<<(tk + 255) / 256, 256>>>(k, cosT, sinT, NKV, tk);
    }

    // Windowed flash attention
    cudaFuncSetAttribute(flash_kernel, cudaFuncAttributeMaxDynamicSharedMemorySize, FLASH_SMEM);
    flash_kernel<<<dim3(Ss / 64, NH, Bb), 256, FLASH_SMEM>>>(q, k, v, ao);

    // Output projection
    sgemm_nt<<<dim3(Ee / 128, M / 128), 256>>>(ao, Wo, out, M, Ee, Ee);
}

// round 3
// speedup vs baseline: 1.6781x; 1.6781x over previous
#include <cuda_runtime.h>
#include <cuda_bf16.h>
#include <cstdint>
#include <math.h>

#define Bb 2
#define Ss 2048
#define Ee 2048
#define NH 16
#define NKV 4
#define HD 128
#define WIN 1024
#define GQ (NH / NKV)
#define MR (Bb * Ss)   // 4096 rows

// ---------------------------------------------------------------------------
// Scratch (device globals; no allocation allowed)
// ---------------------------------------------------------------------------
__device__ float g_q[(size_t)MR * NH * HD];
__device__ float g_k[(size_t)MR * NKV * HD];
__device__ float g_v[(size_t)MR * NKV * HD];
__device__ float g_ao[(size_t)MR * Ee];

__device__ __nv_bfloat16 g_xh[(size_t)MR * Ee],  g_xl[(size_t)MR * Ee];
__device__ __nv_bfloat16 g_aoh[(size_t)MR * Ee], g_aol[(size_t)MR * Ee];
__device__ __nv_bfloat16 g_wqh[(size_t)NH * HD * Ee],  g_wql[(size_t)NH * HD * Ee];
__device__ __nv_bfloat16 g_wkh[(size_t)NKV * HD * Ee], g_wkl[(size_t)NKV * HD * Ee];
__device__ __nv_bfloat16 g_wvh[(size_t)NKV * HD * Ee], g_wvl[(size_t)NKV * HD * Ee];
__device__ __nv_bfloat16 g_woh[(size_t)Ee * Ee],  g_wol[(size_t)Ee * Ee];

// ---------------------------------------------------------------------------
// PTX helpers (baseline sm_80+ instructions only — no tcgen05 on compute_103)
// ---------------------------------------------------------------------------
static __device__ __forceinline__ uint32_t smem_u32(const void* p) {
    uint32_t a;
    asm("{ .reg .u64 t; cvta.to.shared.u64 t, %1; cvt.u32.u64 %0, t; }" : "=r"(a) : "l"(p));
    return a;
}

static __device__ __forceinline__ void ldsm4(uint32_t* r, uint32_t addr) {
    asm volatile("ldmatrix.sync.aligned.m8n8.x4.shared.b16 {%0,%1,%2,%3}, [%4];"
                 : "=r"(r[0]), "=r"(r[1]), "=r"(r[2]), "=r"(r[3]) : "r"(addr));
}

static __device__ __forceinline__ void mma16816(float* d, const uint32_t* a, const uint32_t* b) {
    asm volatile(
        "mma.sync.aligned.m16n8k16.row.col.f32.bf16.bf16.f32 "
        "{%0,%1,%2,%3}, {%4,%5,%6,%7}, {%8,%9}, {%0,%1,%2,%3};"
        : "+f"(d[0]), "+f"(d[1]), "+f"(d[2]), "+f"(d[3])
        : "r"(a[0]), "r"(a[1]), "r"(a[2]), "r"(a[3]), "r"(b[0]), "r"(b[1]));
}

#define CP_ASYNC16(sa, gp) \
    asm volatile("cp.async.cg.shared.global [%0], [%1], 16;" :: "r"(sa), "l"(gp))
#define CP_COMMIT()  asm volatile("cp.async.commit_group;" ::: "memory")
#define CP_WAIT0()   asm volatile("cp.async.wait_group 0;" ::: "memory")

// ---------------------------------------------------------------------------
// fp32 -> bf16 hi/lo split (vectorized x4)
// ---------------------------------------------------------------------------
__global__ void split_bf16(const float* __restrict__ in,
                           __nv_bfloat16* __restrict__ hi,
                           __nv_bfloat16* __restrict__ lo, int n4)
{
    int i = blockIdx.x * blockDim.x + threadIdx.x;
    if (i >= n4) return;
    float4 v = ((const float4*)in)[i];
    float vv[4] = {v.x, v.y, v.z, v.w};
    ushort4 hu, lu;
    unsigned short* hp = &hu.x;
    unsigned short* lp = &lu.x;
#pragma unroll
    for (int j = 0; j < 4; j++) {
        __nv_bfloat16 h = __float2bfloat16(vv[j]);
        __nv_bfloat16 l = __float2bfloat16(vv[j] - __bfloat162float(h));
        hp[j] = __bfloat16_as_ushort(h);
        lp[j] = __bfloat16_as_ushort(l);
    }
    ((ushort4*)hi)[i] = hu;
    ((ushort4*)lo)[i] = lu;
}

// ---------------------------------------------------------------------------
// HMMA bf16-split GEMM (NT): C[M,N] = A[M,K] @ B[N,K]^T, fp32-equivalent.
// 128x128 tile, BK=32, 256 threads (8 warps, 4x2), warp tile 32x64.
// SW64-swizzled smem; cp.async double buffer; mma.sync m16n8k16.
// ---------------------------------------------------------------------------
#define GSTAGE 32768            // Ah(8K) Al(8K) Bh(8K) Bl(8K)
#define GSMEM  (2 * GSTAGE)

// swizzled smem offset for (row r, 16B-chunk c) in a 128x32bf16 tile (64B rows)
static __device__ __forceinline__ uint32_t swoff(int r, int c) {
    return (uint32_t)(r * 64 + ((c ^ ((r >> 1) & 3)) << 4));
}

static __device__ __forceinline__ void ld_tile32(
    uint32_t sdst, const __nv_bfloat16* gsrc, int K, int kt, int t)
{
#pragma unroll
    for (int i = 0; i < 2; i++) {
        int ci = t + i * 256;          // 0..511 chunks: 128 rows x 4 chunks
        int r = ci >> 2, c = ci & 3;
        const char* gp = (const char*)(gsrc + (size_t)r * K + kt * 32 + c * 8);
        CP_ASYNC16(sdst + swoff(r, c), gp);
    }
}

__global__ void __launch_bounds__(256) gemm_mma(
    const __nv_bfloat16* __restrict__ Ah, const __nv_bfloat16* __restrict__ Al,
    const __nv_bfloat16* __restrict__ Bh, const __nv_bfloat16* __restrict__ Bl,
    float* __restrict__ C, int M, int N, int K)
{
    extern __shared__ char rawsm[];
    const uint32_t sb = smem_u32(rawsm);

    const int t    = threadIdx.x;
    const int lane = t & 31;
    const int wid  = t >> 5;
    const int wm   = (wid & 3) * 32;   // warp row offset in tile
    const int wn   = (wid >> 2) * 64;  // warp col offset in tile
    const int bm = blockIdx.y, bn = blockIdx.x;

    const __nv_bfloat16* Ahb = Ah + (size_t)bm * 128 * K;
    const __nv_bfloat16* Alb = Al + (size_t)bm * 128 * K;
    const __nv_bfloat16* Bhb = Bh + (size_t)bn * 128 * K;
    const __nv_bfloat16* Blb = Bl + (size_t)bn * 128 * K;

    float acc[2][8][4];
#pragma unroll
    for (int i = 0; i < 2; i++)
#pragma unroll
        for (int j = 0; j < 8; j++)
#pragma unroll
            for (int r = 0; r < 4; r++) acc[i][j][r] = 0.f;

    const int nchunk = K / 32;

    // Prologue: stage 0
    ld_tile32(sb + 0,     Ahb, K, 0, t);
    ld_tile32(sb + 8192,  Alb, K, 0, t);
    ld_tile32(sb + 16384, Bhb, K, 0, t);
    ld_tile32(sb + 24576, Blb, K, 0, t);
    CP_COMMIT();

    // Per-lane ldmatrix address components
    const int a_row  = lane & 15;            // + wm + mt*16
    const int a_cofs = lane >> 4;            // + ks*2
    const int b_row  = (lane & 7) + ((lane & 16) ? 8 : 0);  // + wn + pt*16
    const int b_cofs = (lane >> 3) & 1;      // + ks*2

    for (int kt = 0; kt < nchunk; kt++) {
        CP_WAIT0();
        __syncthreads();
        if (kt + 1 < nchunk) {
            const uint32_t sn = sb + (uint32_t)((kt + 1) & 1) * GSTAGE;
            ld_tile32(sn + 0,     Ahb, K, kt + 1, t);
            ld_tile32(sn + 8192,  Alb, K, kt + 1, t);
            ld_tile32(sn + 16384, Bhb, K, kt + 1, t);
            ld_tile32(sn + 24576, Blb, K, kt + 1, t);
            CP_COMMIT();
        }
        const uint32_t so = sb + (uint32_t)(kt & 1) * GSTAGE;

#pragma unroll
        for (int ks = 0; ks < 2; ks++) {
            const int c = ks * 2;
            uint32_t ah[2][4], al[2][4];
#pragma unroll
            for (int mt = 0; mt < 2; mt++) {
                int r = wm + mt * 16 + a_row;
                ldsm4(ah[mt], so + 0    + swoff(r, c + a_cofs));
                ldsm4(al[mt], so + 8192 + swoff(r, c + a_cofs));
            }
#pragma unroll
            for (int pt = 0; pt < 4; pt++) {
                int r = wn + pt * 16 + b_row;
                uint32_t bh[4], bl[4];
                ldsm4(bh, so + 16384 + swoff(r, c + b_cofs));
                ldsm4(bl, so + 24576 + swoff(r, c + b_cofs));
#pragma unroll
                for (int mt = 0; mt < 2; mt++) {
#pragma unroll
                    for (int sub = 0; sub < 2; sub++) {
                        float* d = acc[mt][pt * 2 + sub];
                        mma16816(d, ah[mt], bh + sub * 2);
                        mma16816(d, ah[mt], bl + sub * 2);
                        mma16816(d, al[mt], bh + sub * 2);
                    }
                }
            }
        }
        __syncthreads();
    }

    // Epilogue: registers -> gmem (float2 per lane per tile-half)
    const int gr = lane >> 2, tg = lane & 3;
#pragma unroll
    for (int mt = 0; mt < 2; mt++) {
#pragma unroll
        for (int nt = 0; nt < 8; nt++) {
            int row0 = bm * 128 + wm + mt * 16 + gr;
            int col  = bn * 128 + wn + nt * 8 + tg * 2;
            float* d = acc[mt][nt];
            *(float2*)(C + (size_t)row0 * N + col)       = make_float2(d[0], d[1]);
            *(float2*)(C + (size_t)(row0 + 8) * N + col) = make_float2(d[2], d[3]);
        }
    }
}

// ---------------------------------------------------------------------------
// RoPE (duplicated-half layout). data: [B, S, nheads, HD].
// ---------------------------------------------------------------------------
__global__ void rope_kernel(float* __restrict__ data,
                            const float* __restrict__ cosT,
                            const float* __restrict__ sinT, int nheads, int total)
{
    int i = blockIdx.x * blockDim.x + threadIdx.x;
    if (i >= total) return;
    int d    = i & 63;
    int rest = i >> 6;
    int h    = rest % nheads;
    int bs   = rest / nheads;
    int s    = bs & (Ss - 1);
    size_t base = ((size_t)bs * nheads + h) * HD;
    float x1 = data[base + d];
    float x2 = data[base + d + 64];
    float c1 = cosT[s * HD + d],      s1 = sinT[s * HD + d];
    float c2 = cosT[s * HD + d + 64], s2 = sinT[s * HD + d + 64];
    data[base + d]      = x1 * c1 - x2 * s1;
    data[base + d + 64] = x2 * c2 + x1 * s2;
}

// ---------------------------------------------------------------------------
// Windowed-causal flash attention, fp32 (unchanged from R1 passing version)
// ---------------------------------------------------------------------------
#define QLD 132
#define PLD 68
#define FLASH_SMEM ((2 * 64 * QLD + 64 * PLD) * 4)

__global__ void __launch_bounds__(256, 2) flash_kernel(
    const float* __restrict__ gq, const float* __restrict__ gk,
    const float* __restrict__ gv, float* __restrict__ gao)
{
    extern __shared__ float sm[];
    float* Qs  = sm;
    float* KVs = sm + 64 * QLD;
    float* Ps  = sm + 2 * 64 * QLD;

    const int t  = threadIdx.x;
    const int qt = blockIdx.x, h = blockIdx.y, b = blockIdx.z;
    const int hk = h / GQ;
    const int q0 = qt * 64;
    const int tx = t & 15, ty = t >> 4;
    const float scale = 0.08838834764831845f;

#pragma unroll
    for (int r = 0; r < 8; r++) {
        int lin = t + r * 256;
        int row = lin >> 5, c4 = lin & 31;
        float4 v = *(const float4*)(gq + (((size_t)(b * Ss + q0 + row)) * NH + h) * HD + c4 * 4);
        v.x *= scale; v.y *= scale; v.z *= scale; v.w *= scale;
        *(float4*)(Qs + row * QLD + c4 * 4) = v;
    }

    float m[4], l[4], o[4][8];
#pragma unroll
    for (int i = 0; i < 4; i++) {
        m[i] = -1e30f; l[i] = 0.f;
#pragma unroll
        for (int c = 0; c < 8; c++) o[i][c] = 0.f;
    }

    int jstart = q0 - (WIN - 1); if (jstart < 0) jstart = 0;
    const int jt0 = jstart >> 6;
    const int jt1 = qt;

    for (int jt = jt0; jt <= jt1; jt++) {
        const int j0 = jt * 64;
        __syncthreads();
#pragma unroll
        for (int r = 0; r < 8; r++) {
            int lin = t + r * 256;
            int row = lin >> 5, c4 = lin & 31;
            *(float4*)(KVs + row * QLD + c4 * 4) =
                *(const float4*)(gk + (((size_t)(b * Ss + j0 + row)) * NKV + hk) * HD + c4 * 4);
        }
        __syncthreads();

        float s[4][4];
#pragma unroll
        for (int i = 0; i < 4; i++)
#pragma unroll
            for (int j = 0; j < 4; j++) s[i][j] = 0.f;

#pragma unroll 4
        for (int kk = 0; kk < HD; kk += 4) {
            float4 qf[4], kf[4];
#pragma unroll
            for (int i = 0; i < 4; i++) qf[i] = *(const float4*)(Qs + (ty * 4 + i) * QLD + kk);
#pragma unroll
            for (int j = 0; j < 4; j++) kf[j] = *(const float4*)(KVs + (tx * 4 + j) * QLD + kk);
#pragma unroll
            for (int i = 0; i < 4; i++)
#pragma unroll
                for (int j = 0; j < 4; j++)
                    s[i][j] += qf[i].x * kf[j].x + qf[i].y * kf[j].y
                             + qf[i].z * kf[j].z + qf[i].w * kf[j].w;
        }

        float mn[4];
#pragma unroll
        for (int i = 0; i < 4; i++) {
            int gi = q0 + ty * 4 + i;
            float rm = m[i];
#pragma unroll
            for (int j = 0; j < 4; j++) {
                int dist = gi - (j0 + tx * 4 + j);
                if (dist < 0 || dist >= WIN) s[i][j] = -1e30f;
                rm = fmaxf(rm, s[i][j]);
            }
            mn[i] = rm;
        }
#pragma unroll
        for (int i = 0; i < 4; i++)
#pragma unroll
            for (int off = 8; off; off >>= 1)
                mn[i] = fmaxf(mn[i], __shfl_xor_sync(0xffffffffu, mn[i], off));

#pragma unroll
        for (int i = 0; i < 4; i++) {
            float alpha = __expf(m[i] - mn[i]);
            l[i] *= alpha;
#pragma unroll
            for (int c = 0; c < 8; c++) o[i][c] *= alpha;
            float rs = 0.f;
#pragma unroll
            for (int j = 0; j < 4; j++) {
                float p = (s[i][j] > -1e29f) ? __expf(s[i][j] - mn[i]) : 0.f;
                s[i][j] = p;
                rs += p;
            }
#pragma unroll
            for (int off = 8; off; off >>= 1)
                rs += __shfl_xor_sync(0xffffffffu, rs, off);
            l[i] += rs;
            m[i] = mn[i];
        }

#pragma unroll
        for (int i = 0; i < 4; i++)
            *(float4*)(Ps + (ty * 4 + i) * PLD + tx * 4) =
                make_float4(s[i][0], s[i][1], s[i][2], s[i][3]);
        __syncthreads();

#pragma unroll
        for (int r = 0; r < 8; r++) {
            int lin = t + r * 256;
            int row = lin >> 5, c4 = lin & 31;
            *(float4*)(KVs + row * QLD + c4 * 4) =
                *(const float4*)(gv + (((size_t)(b * Ss + j0 + row)) * NKV + hk) * HD + c4 * 4);
        }
        __syncthreads();

#pragma unroll 4
        for (int j = 0; j < 64; j++) {
            float4 v0 = *(const float4*)(KVs + j * QLD + tx * 8);
            float4 v1 = *(const float4*)(KVs + j * QLD + tx * 8 + 4);
#pragma unroll
            for (int i = 0; i < 4; i++) {
                float p = Ps[(ty * 4 + i) * PLD + j];
                o[i][0] += p * v0.x; o[i][1] += p * v0.y;
                o[i][2] += p * v0.z; o[i][3] += p * v0.w;
                o[i][4] += p * v1.x; o[i][5] += p * v1.y;
                o[i][6] += p * v1.z; o[i][7] += p * v1.w;
            }
        }
    }

#pragma unroll
    for (int i = 0; i < 4; i++) {
        float inv = 1.f / l[i];
        float* op = gao + (((size_t)(b * Ss + q0 + ty * 4 + i)) * NH + h) * HD + tx * 8;
        *(float4*)(op)     = make_float4(o[i][0] * inv, o[i][1] * inv, o[i][2] * inv, o[i][3] * inv);
        *(float4*)(op + 4) = make_float4(o[i][4] * inv, o[i][5] * inv, o[i][6] * inv, o[i][7] * inv);
    }
}

// ---------------------------------------------------------------------------
extern "C" void kernel_launch(void* const* d_in, const int* in_sizes, int n_in,
                              void* d_out, int out_size)
{
    const float* x    = (const float*)d_in[0];
    const float* cosT = (const float*)d_in[1];
    const float* sinT = (const float*)d_in[2];
    const float* Wq   = (const float*)d_in[3];
    const float* Wk   = (const float*)d_in[4];
    const float* Wv   = (const float*)d_in[5];
    const float* Wo   = (const float*)d_in[6];
    float* out = (float*)d_out;

    void *pq, *pk, *pv, *pao;
    void *pxh, *pxl, *paoh, *paol;
    void *pwqh, *pwql, *pwkh, *pwkl, *pwvh, *pwvl, *pwoh, *pwol;
    cudaGetSymbolAddress(&pq,  g_q);   cudaGetSymbolAddress(&pk,  g_k);
    cudaGetSymbolAddress(&pv,  g_v);   cudaGetSymbolAddress(&pao, g_ao);
    cudaGetSymbolAddress(&pxh, g_xh);  cudaGetSymbolAddress(&pxl, g_xl);
    cudaGetSymbolAddress(&paoh, g_aoh); cudaGetSymbolAddress(&paol, g_aol);
    cudaGetSymbolAddress(&pwqh, g_wqh); cudaGetSymbolAddress(&pwql, g_wql);
    cudaGetSymbolAddress(&pwkh, g_wkh); cudaGetSymbolAddress(&pwkl, g_wkl);
    cudaGetSymbolAddress(&pwvh, g_wvh); cudaGetSymbolAddress(&pwvl, g_wvl);
    cudaGetSymbolAddress(&pwoh, g_woh); cudaGetSymbolAddress(&pwol, g_wol);

    float* q  = (float*)pq;  float* k = (float*)pk;
    float* v  = (float*)pv;  float* ao = (float*)pao;
    __nv_bfloat16 *xh = (__nv_bfloat16*)pxh,  *xl = (__nv_bfloat16*)pxl;
    __nv_bfloat16 *aoh = (__nv_bfloat16*)paoh, *aol = (__nv_bfloat16*)paol;
    __nv_bfloat16 *wqh = (__nv_bfloat16*)pwqh, *wql = (__nv_bfloat16*)pwql;
    __nv_bfloat16 *wkh = (__nv_bfloat16*)pwkh, *wkl = (__nv_bfloat16*)pwkl;
    __nv_bfloat16 *wvh = (__nv_bfloat16*)pwvh, *wvl = (__nv_bfloat16*)pwvl;
    __nv_bfloat16 *woh = (__nv_bfloat16*)pwoh, *wol = (__nv_bfloat16*)pwol;

    // Splits: activations + weights
    {
        int n4 = MR * Ee / 4;
        split_bf16<<<(n4 + 255) / 256, 256>>>(x, xh, xl, n4);
        int w4 = NH * HD * Ee / 4;
        split_bf16<<<(w4 + 255) / 256, 256>>>(Wq, wqh, wql, w4);
        int k4 = NKV * HD * Ee / 4;
        split_bf16<<<(k4 + 255) / 256, 256>>>(Wk, wkh, wkl, k4);
        split_bf16<<<(k4 + 255) / 256, 256>>>(Wv, wvh, wvl, k4);
        int o4 = Ee * Ee / 4;
        split_bf16<<<(o4 + 255) / 256, 256>>>(Wo, woh, wol, o4);
    }

    cudaFuncSetAttribute(gemm_mma, cudaFuncAttributeMaxDynamicSharedMemorySize, GSMEM);

    // QKV projections (HMMA tensor cores, fp32-equivalent via hi/lo split)
    gemm_mma<<<dim3((NH * HD) / 128, MR / 128), 256, GSMEM>>>(xh, xl, wqh, wql, q, MR, NH * HD, Ee);
    gemm_mma<<<dim3((NKV * HD) / 128, MR / 128), 256, GSMEM>>>(xh, xl, wkh, wkl, k, MR, NKV * HD, Ee);
    gemm_mma<<<dim3((NKV * HD) / 128, MR / 128), 256, GSMEM>>>(xh, xl, wvh, wvl, v, MR, NKV * HD, Ee);

    // RoPE
    {
        int tq = MR * NH * 64;
        rope_kernel<<<(tq + 255) / 256, 256>>>(q, cosT, sinT, NH, tq);
        int tk = MR * NKV * 64;
        rope_kernel<<<(tk + 255) / 256, 256>>>(k, cosT, sinT, NKV, tk);
    }

    // Windowed flash attention (fp32)
    cudaFuncSetAttribute(flash_kernel, cudaFuncAttributeMaxDynamicSharedMemorySize, FLASH_SMEM);
    flash_kernel<<<dim3(Ss / 64, NH, Bb), 256, FLASH_SMEM>>>(q, k, v, ao);

    // Output projection
    {
        int n4 = MR * Ee / 4;
        split_bf16<<<(n4 + 255) / 256, 256>>>(ao, aoh, aol, n4);
    }
    gemm_mma<<<dim3(Ee / 128, MR / 128), 256, GSMEM>>>(aoh, aol, woh, wol, out, MR, Ee, Ee);
}

// round 5
// speedup vs baseline: 3.5096x; 2.0914x over previous
#include <cuda_runtime.h>
#include <cuda_bf16.h>
#include <cstdint>
#include <math.h>

#define Bb 2
#define Ss 2048
#define Ee 2048
#define NH 16
#define NKV 4
#define HD 128
#define WIN 1024
#define GQ (NH / NKV)
#define MR (Bb * Ss)   // 4096 rows

// ---------------------------------------------------------------------------
// Scratch (device globals; no allocation allowed)
// ---------------------------------------------------------------------------
__device__ float g_q[(size_t)MR * NH * HD];
__device__ float g_k[(size_t)MR * NKV * HD];
__device__ float g_v[(size_t)MR * NKV * HD];
__device__ float g_ao[(size_t)MR * Ee];

__device__ __nv_bfloat16 g_xh[(size_t)MR * Ee],  g_xl[(size_t)MR * Ee];
__device__ __nv_bfloat16 g_aoh[(size_t)MR * Ee], g_aol[(size_t)MR * Ee];
__device__ __nv_bfloat16 g_wqh[(size_t)NH * HD * Ee],  g_wql[(size_t)NH * HD * Ee];
__device__ __nv_bfloat16 g_wkh[(size_t)NKV * HD * Ee], g_wkl[(size_t)NKV * HD * Ee];
__device__ __nv_bfloat16 g_wvh[(size_t)NKV * HD * Ee], g_wvl[(size_t)NKV * HD * Ee];
__device__ __nv_bfloat16 g_woh[(size_t)Ee * Ee],  g_wol[(size_t)Ee * Ee];

__device__ __nv_bfloat16 g_qh[(size_t)MR * NH * HD],  g_ql[(size_t)MR * NH * HD];
__device__ __nv_bfloat16 g_kh[(size_t)MR * NKV * HD], g_kl[(size_t)MR * NKV * HD];
__device__ __nv_bfloat16 g_vh[(size_t)MR * NKV * HD], g_vl[(size_t)MR * NKV * HD];

// ---------------------------------------------------------------------------
// PTX helpers (baseline sm_80+ only — tcgen05 is rejected by compute_103)
// ---------------------------------------------------------------------------
static __device__ __forceinline__ uint32_t smem_u32(const void* p) {
    uint32_t a;
    asm("{ .reg .u64 t; cvta.to.shared.u64 t, %1; cvt.u32.u64 %0, t; }" : "=r"(a) : "l"(p));
    return a;
}
static __device__ __forceinline__ void ldsm4(uint32_t* r, uint32_t addr) {
    asm volatile("ldmatrix.sync.aligned.m8n8.x4.shared.b16 {%0,%1,%2,%3}, [%4];"
                 : "=r"(r[0]), "=r"(r[1]), "=r"(r[2]), "=r"(r[3]) : "r"(addr));
}
static __device__ __forceinline__ void ldsm4t(uint32_t* r, uint32_t addr) {
    asm volatile("ldmatrix.sync.aligned.m8n8.x4.trans.shared.b16 {%0,%1,%2,%3}, [%4];"
                 : "=r"(r[0]), "=r"(r[1]), "=r"(r[2]), "=r"(r[3]) : "r"(addr));
}
static __device__ __forceinline__ void mma16816(float* d, const uint32_t* a, const uint32_t* b) {
    asm volatile(
        "mma.sync.aligned.m16n8k16.row.col.f32.bf16.bf16.f32 "
        "{%0,%1,%2,%3}, {%4,%5,%6,%7}, {%8,%9}, {%0,%1,%2,%3};"
        : "+f"(d[0]), "+f"(d[1]), "+f"(d[2]), "+f"(d[3])
        : "r"(a[0]), "r"(a[1]), "r"(a[2]), "r"(a[3]), "r"(b[0]), "r"(b[1]));
}

#define CP_ASYNC16(sa, gp) \
    asm volatile("cp.async.cg.shared.global [%0], [%1], 16;" :: "r"(sa), "l"(gp))
#define CP_COMMIT()  asm volatile("cp.async.commit_group;" ::: "memory")
#define CP_WAIT0()   asm volatile("cp.async.wait_group 0;" ::: "memory")

// swizzled offset for (row r, 16B-chunk c) in a 64B-row subtile
static __device__ __forceinline__ uint32_t swoff(int r, int c) {
    return (uint32_t)(r * 64 + ((c ^ ((r >> 1) & 3)) << 4));
}

// pack two floats -> bf16x2 hi reg, lo reg via out-param
static __device__ __forceinline__ uint32_t packsplit(float a, float b, uint32_t& lo) {
    __nv_bfloat162 h = __floats2bfloat162_rn(a, b);
    float2 hf = __bfloat1622float2(h);
    __nv_bfloat162 l = __floats2bfloat162_rn(a - hf.x, b - hf.y);
    lo = *reinterpret_cast<uint32_t*>(&l);
    return *reinterpret_cast<uint32_t*>(&h);
}

// ---------------------------------------------------------------------------
// fp32 -> bf16 hi/lo split (x4), optional scale folded in
// ---------------------------------------------------------------------------
__global__ void split_bf16(const float* __restrict__ in,
                           __nv_bfloat16* __restrict__ hi,
                           __nv_bfloat16* __restrict__ lo, int n4, float scale)
{
    int i = blockIdx.x * blockDim.x + threadIdx.x;
    if (i >= n4) return;
    float4 v = ((const float4*)in)[i];
    float vv[4] = {v.x * scale, v.y * scale, v.z * scale, v.w * scale};
    ushort4 hu, lu;
    unsigned short* hp = &hu.x;
    unsigned short* lp = &lu.x;
#pragma unroll
    for (int j = 0; j < 4; j++) {
        __nv_bfloat16 h = __float2bfloat16(vv[j]);
        __nv_bfloat16 l = __float2bfloat16(vv[j] - __bfloat162float(h));
        hp[j] = __bfloat16_as_ushort(h);
        lp[j] = __bfloat16_as_ushort(l);
    }
    ((ushort4*)hi)[i] = hu;
    ((ushort4*)lo)[i] = lu;
}

// ---------------------------------------------------------------------------
// HMMA bf16-split GEMM (NT) — unchanged from R3 (passing)
// ---------------------------------------------------------------------------
#define GSTAGE 32768
#define GSMEM  (2 * GSTAGE)

static __device__ __forceinline__ void ld_tile32(
    uint32_t sdst, const __nv_bfloat16* gsrc, int K, int kt, int t)
{
#pragma unroll
    for (int i = 0; i < 2; i++) {
        int ci = t + i * 256;
        int r = ci >> 2, c = ci & 3;
        const char* gp = (const char*)(gsrc + (size_t)r * K + kt * 32 + c * 8);
        CP_ASYNC16(sdst + swoff(r, c), gp);
    }
}

__global__ void __launch_bounds__(256) gemm_mma(
    const __nv_bfloat16* __restrict__ Ah, const __nv_bfloat16* __restrict__ Al,
    const __nv_bfloat16* __restrict__ Bh, const __nv_bfloat16* __restrict__ Bl,
    float* __restrict__ C, int M, int N, int K)
{
    extern __shared__ char rawsm[];
    const uint32_t sb = smem_u32(rawsm);

    const int t    = threadIdx.x;
    const int lane = t & 31;
    const int wid  = t >> 5;
    const int wm   = (wid & 3) * 32;
    const int wn   = (wid >> 2) * 64;
    const int bm = blockIdx.y, bn = blockIdx.x;

    const __nv_bfloat16* Ahb = Ah + (size_t)bm * 128 * K;
    const __nv_bfloat16* Alb = Al + (size_t)bm * 128 * K;
    const __nv_bfloat16* Bhb = Bh + (size_t)bn * 128 * K;
    const __nv_bfloat16* Blb = Bl + (size_t)bn * 128 * K;

    float acc[2][8][4];
#pragma unroll
    for (int i = 0; i < 2; i++)
#pragma unroll
        for (int j = 0; j < 8; j++)
#pragma unroll
            for (int r = 0; r < 4; r++) acc[i][j][r] = 0.f;

    const int nchunk = K / 32;

    ld_tile32(sb + 0,     Ahb, K, 0, t);
    ld_tile32(sb + 8192,  Alb, K, 0, t);
    ld_tile32(sb + 16384, Bhb, K, 0, t);
    ld_tile32(sb + 24576, Blb, K, 0, t);
    CP_COMMIT();

    const int a_row  = lane & 15;
    const int a_cofs = lane >> 4;
    const int b_row  = (lane & 7) + ((lane & 16) ? 8 : 0);
    const int b_cofs = (lane >> 3) & 1;

    for (int kt = 0; kt < nchunk; kt++) {
        CP_WAIT0();
        __syncthreads();
        if (kt + 1 < nchunk) {
            const uint32_t sn = sb + (uint32_t)((kt + 1) & 1) * GSTAGE;
            ld_tile32(sn + 0,     Ahb, K, kt + 1, t);
            ld_tile32(sn + 8192,  Alb, K, kt + 1, t);
            ld_tile32(sn + 16384, Bhb, K, kt + 1, t);
            ld_tile32(sn + 24576, Blb, K, kt + 1, t);
            CP_COMMIT();
        }
        const uint32_t so = sb + (uint32_t)(kt & 1) * GSTAGE;

#pragma unroll
        for (int ks = 0; ks < 2; ks++) {
            const int c = ks * 2;
            uint32_t ah[2][4], al[2][4];
#pragma unroll
            for (int mt = 0; mt < 2; mt++) {
                int r = wm + mt * 16 + a_row;
                ldsm4(ah[mt], so + 0    + swoff(r, c + a_cofs));
                ldsm4(al[mt], so + 8192 + swoff(r, c + a_cofs));
            }
#pragma unroll
            for (int pt = 0; pt < 4; pt++) {
                int r = wn + pt * 16 + b_row;
                uint32_t bh[4], bl[4];
                ldsm4(bh, so + 16384 + swoff(r, c + b_cofs));
                ldsm4(bl, so + 24576 + swoff(r, c + b_cofs));
#pragma unroll
                for (int mt = 0; mt < 2; mt++) {
#pragma unroll
                    for (int sub = 0; sub < 2; sub++) {
                        float* d = acc[mt][pt * 2 + sub];
                        mma16816(d, ah[mt], bh + sub * 2);
                        mma16816(d, ah[mt], bl + sub * 2);
                        mma16816(d, al[mt], bh + sub * 2);
                    }
                }
            }
        }
        __syncthreads();
    }

    const int gr = lane >> 2, tg = lane & 3;
#pragma unroll
    for (int mt = 0; mt < 2; mt++) {
#pragma unroll
        for (int nt = 0; nt < 8; nt++) {
            int row0 = bm * 128 + wm + mt * 16 + gr;
            int col  = bn * 128 + wn + nt * 8 + tg * 2;
            float* d = acc[mt][nt];
            *(float2*)(C + (size_t)row0 * N + col)       = make_float2(d[0], d[1]);
            *(float2*)(C + (size_t)(row0 + 8) * N + col) = make_float2(d[2], d[3]);
        }
    }
}

// ---------------------------------------------------------------------------
// RoPE (duplicated-half layout). data: [B, S, nheads, HD].
// ---------------------------------------------------------------------------
__global__ void rope_kernel(float* __restrict__ data,
                            const float* __restrict__ cosT,
                            const float* __restrict__ sinT, int nheads, int total)
{
    int i = blockIdx.x * blockDim.x + threadIdx.x;
    if (i >= total) return;
    int d    = i & 63;
    int rest = i >> 6;
    int h    = rest % nheads;
    int bs   = rest / nheads;
    int s    = bs & (Ss - 1);
    size_t base = ((size_t)bs * nheads + h) * HD;
    float x1 = data[base + d];
    float x2 = data[base + d + 64];
    float c1 = cosT[s * HD + d],      s1 = sinT[s * HD + d];
    float c2 = cosT[s * HD + d + 64], s2 = sinT[s * HD + d + 64];
    data[base + d]      = x1 * c1 - x2 * s1;
    data[base + d + 64] = x2 * c2 + x1 * s2;
}

// ---------------------------------------------------------------------------
// HMMA windowed-causal flash attention (fp32-equivalent via bf16 hi/lo split)
// CTA: 128 q-rows x one head x one batch. 8 warps x 16 rows. j-tile = 64 keys.
// smem: Qh(32K) Ql(32K) | 2 stages x [Kh(16K) Kl(16K) Vh(16K) Vl(16K)]
// ---------------------------------------------------------------------------
#define FQH  0
#define FQL  32768
#define FST  65536
#define FSTG 65536
#define FLASH_SMEM (FST + 2 * FSTG)   // 196608

static __device__ __forceinline__ void flash_ld_q(
    uint32_t sq, const __nv_bfloat16* gq, int bs0, int h, int t)
{
#pragma unroll
    for (int i = 0; i < 8; i++) {
        int id = t + i * 256;
        int sub = id >> 9, rem = id & 511;
        int r = rem >> 2, c = rem & 3;
        const char* gp = (const char*)(gq + ((size_t)(bs0 + r) * NH + h) * HD + sub * 32 + c * 8);
        CP_ASYNC16(sq + sub * 8192 + swoff(r, c), gp);
    }
}
static __device__ __forceinline__ void flash_ld_kv(
    uint32_t sdst, const __nv_bfloat16* gsrc, int bs0, int hk, int t)
{
#pragma unroll
    for (int i = 0; i < 4; i++) {
        int id = t + i * 256;
        int sub = id >> 8, rem = id & 255;
        int r = rem >> 2, c = rem & 3;
        const char* gp = (const char*)(gsrc + ((size_t)(bs0 + r) * NKV + hk) * HD + sub * 32 + c * 8);
        CP_ASYNC16(sdst + sub * 4096 + swoff(r, c), gp);
    }
}

__global__ void __launch_bounds__(256) flash_mma(
    const __nv_bfloat16* __restrict__ qh, const __nv_bfloat16* __restrict__ ql,
    const __nv_bfloat16* __restrict__ kh, const __nv_bfloat16* __restrict__ kl,
    const __nv_bfloat16* __restrict__ vh, const __nv_bfloat16* __restrict__ vl,
    float* __restrict__ gao)
{
    extern __shared__ char rawsm[];
    const uint32_t sb = smem_u32(rawsm);

    const int t    = threadIdx.x;
    const int lane = t & 31;
    const int wid  = t >> 5;
    const int wm   = wid * 16;
    const int qt = blockIdx.x, h = blockIdx.y, b = blockIdx.z;
    const int hk = h / GQ;
    const int q0 = qt * 128;
    const int bs = b * Ss;

    const int a_row  = lane & 15;
    const int a_cofs = lane >> 4;
    const int b_row  = (lane & 7) + ((lane & 16) ? 8 : 0);
    const int b_cofs = (lane >> 3) & 1;
    // V (.trans B-fragment) addressing: lanes 0-15 -> key rows 0-15 (chunk c),
    // lanes 16-31 -> same rows, chunk c+1
    const int v_row  = lane & 15;
    const int v_cofs = lane >> 4;

    float m0 = -1e30f, m1 = -1e30f, l0 = 0.f, l1 = 0.f;
    float o[16][4];
#pragma unroll
    for (int j = 0; j < 16; j++)
#pragma unroll
        for (int r = 0; r < 4; r++) o[j][r] = 0.f;

    int lo = q0 - (WIN - 1); if (lo < 0) lo = 0;
    const int jt0 = lo >> 6;
    const int jt1 = (q0 + 127) >> 6;

    flash_ld_q(sb + FQH, qh, bs + q0, h, t);
    flash_ld_q(sb + FQL, ql, bs + q0, h, t);
    {
        const uint32_t s0 = sb + FST + (uint32_t)(jt0 & 1) * FSTG;
        flash_ld_kv(s0 + 0,     kh, bs + jt0 * 64, hk, t);
        flash_ld_kv(s0 + 16384, kl, bs + jt0 * 64, hk, t);
        flash_ld_kv(s0 + 32768, vh, bs + jt0 * 64, hk, t);
        flash_ld_kv(s0 + 49152, vl, bs + jt0 * 64, hk, t);
    }
    CP_COMMIT();

    const int gi0 = q0 + wm + (lane >> 2);
    const int gi1 = gi0 + 8;
    const int colq = (lane & 3) * 2;

    for (int jt = jt0; jt <= jt1; jt++) {
        const int j0 = jt * 64;
        CP_WAIT0();
        __syncthreads();
        if (jt + 1 <= jt1) {
            const uint32_t sn = sb + FST + (uint32_t)((jt + 1) & 1) * FSTG;
            flash_ld_kv(sn + 0,     kh, bs + (jt + 1) * 64, hk, t);
            flash_ld_kv(sn + 16384, kl, bs + (jt + 1) * 64, hk, t);
            flash_ld_kv(sn + 32768, vh, bs + (jt + 1) * 64, hk, t);
            flash_ld_kv(sn + 49152, vl, bs + (jt + 1) * 64, hk, t);
            CP_COMMIT();
        }
        const uint32_t st = sb + FST + (uint32_t)(jt & 1) * FSTG;

        // ---- scores S[128x64] (this warp: rows wm..wm+15) ----
        float s[8][4];
#pragma unroll
        for (int j = 0; j < 8; j++)
#pragma unroll
            for (int r = 0; r < 4; r++) s[j][r] = 0.f;

#pragma unroll
        for (int kc = 0; kc < 8; kc++) {
            const int sub = kc >> 1, cb = (kc & 1) * 2;
            uint32_t ah[4], al[4];
            uint32_t qa = sb + FQH + sub * 8192 + swoff(wm + a_row, cb + a_cofs);
            ldsm4(ah, qa);
            ldsm4(al, qa + 32768);
#pragma unroll
            for (int nt = 0; nt < 4; nt++) {
                uint32_t ka = st + sub * 4096 + swoff(nt * 16 + b_row, cb + b_cofs);
                uint32_t bh[4], bl[4];
                ldsm4(bh, ka);
                ldsm4(bl, ka + 16384);
#pragma unroll
                for (int su = 0; su < 2; su++) {
                    float* d = s[nt * 2 + su];
                    mma16816(d, ah, bh + su * 2);
                    mma16816(d, ah, bl + su * 2);
                    mma16816(d, al, bh + su * 2);
                }
            }
        }

        // ---- mask + online softmax ----
        float mt0 = -1e30f, mt1 = -1e30f;
#pragma unroll
        for (int j = 0; j < 8; j++) {
            int c0 = j0 + j * 8 + colq;
#pragma unroll
            for (int e = 0; e < 2; e++) {
                int cc = c0 + e;
                int d0 = gi0 - cc, d1 = gi1 - cc;
                if (d0 < 0 || d0 >= WIN) s[j][e] = -1e30f;
                if (d1 < 0 || d1 >= WIN) s[j][2 + e] = -1e30f;
                mt0 = fmaxf(mt0, s[j][e]);
                mt1 = fmaxf(mt1, s[j][2 + e]);
            }
        }
#pragma unroll
        for (int off = 1; off <= 2; off <<= 1) {
            mt0 = fmaxf(mt0, __shfl_xor_sync(0xffffffffu, mt0, off));
            mt1 = fmaxf(mt1, __shfl_xor_sync(0xffffffffu, mt1, off));
        }
        float mn0 = fmaxf(m0, mt0), mn1 = fmaxf(m1, mt1);
        float al0 = __expf(m0 - mn0), al1 = __expf(m1 - mn1);
        m0 = mn0; m1 = mn1;

        float rs0 = 0.f, rs1 = 0.f;
#pragma unroll
        for (int j = 0; j < 8; j++) {
#pragma unroll
            for (int e = 0; e < 2; e++) {
                float p0 = (s[j][e]     > -1e29f) ? __expf(s[j][e]     - mn0) : 0.f;
                float p1 = (s[j][2 + e] > -1e29f) ? __expf(s[j][2 + e] - mn1) : 0.f;
                s[j][e] = p0; s[j][2 + e] = p1;
                rs0 += p0; rs1 += p1;
            }
        }
#pragma unroll
        for (int off = 1; off <= 2; off <<= 1) {
            rs0 += __shfl_xor_sync(0xffffffffu, rs0, off);
            rs1 += __shfl_xor_sync(0xffffffffu, rs1, off);
        }
        l0 = l0 * al0 + rs0;
        l1 = l1 * al1 + rs1;
#pragma unroll
        for (int j = 0; j < 16; j++) {
            o[j][0] *= al0; o[j][1] *= al0;
            o[j][2] *= al1; o[j][3] *= al1;
        }

        // ---- O += P @ V ----
#pragma unroll
        for (int kc2 = 0; kc2 < 4; kc2++) {
            uint32_t phi[4], plo[4];
            phi[0] = packsplit(s[2 * kc2][0],     s[2 * kc2][1],     plo[0]);
            phi[1] = packsplit(s[2 * kc2][2],     s[2 * kc2][3],     plo[1]);
            phi[2] = packsplit(s[2 * kc2 + 1][0], s[2 * kc2 + 1][1], plo[2]);
            phi[3] = packsplit(s[2 * kc2 + 1][2], s[2 * kc2 + 1][3], plo[3]);
#pragma unroll
            for (int nt = 0; nt < 8; nt++) {
                const int sub = nt >> 1, cb = (nt & 1) * 2;
                uint32_t va = st + 32768 + sub * 4096
                            + swoff(kc2 * 16 + v_row, cb + v_cofs);
                uint32_t vhf[4], vlf[4];
                ldsm4t(vhf, va);
                ldsm4t(vlf, va + 16384);
#pragma unroll
                for (int su = 0; su < 2; su++) {
                    float* d = o[nt * 2 + su];
                    mma16816(d, phi, vhf + su * 2);
                    mma16816(d, phi, vlf + su * 2);
                    mma16816(d, plo, vhf + su * 2);
                }
            }
        }
    }

    // epilogue: normalize + write
    float inv0 = 1.f / l0, inv1 = 1.f / l1;
#pragma unroll
    for (int j = 0; j < 16; j++) {
        int col = j * 8 + colq;
        *(float2*)(gao + ((size_t)(bs + gi0) * NH + h) * HD + col) =
            make_float2(o[j][0] * inv0, o[j][1] * inv0);
        *(float2*)(gao + ((size_t)(bs + gi1) * NH + h) * HD + col) =
            make_float2(o[j][2] * inv1, o[j][3] * inv1);
    }
}

// ---------------------------------------------------------------------------
extern "C" void kernel_launch(void* const* d_in, const int* in_sizes, int n_in,
                              void* d_out, int out_size)
{
    const float* x    = (const float*)d_in[0];
    const float* cosT = (const float*)d_in[1];
    const float* sinT = (const float*)d_in[2];
    const float* Wq   = (const float*)d_in[3];
    const float* Wk   = (const float*)d_in[4];
    const float* Wv   = (const float*)d_in[5];
    const float* Wo   = (const float*)d_in[6];
    float* out = (float*)d_out;

    void *pq, *pk, *pv, *pao;
    void *pxh, *pxl, *paoh, *paol;
    void *pwqh, *pwql, *pwkh, *pwkl, *pwvh, *pwvl, *pwoh, *pwol;
    void *pqh, *pql, *pkh, *pkl, *pvh, *pvl;
    cudaGetSymbolAddress(&pq,  g_q);   cudaGetSymbolAddress(&pk,  g_k);
    cudaGetSymbolAddress(&pv,  g_v);   cudaGetSymbolAddress(&pao, g_ao);
    cudaGetSymbolAddress(&pxh, g_xh);  cudaGetSymbolAddress(&pxl, g_xl);
    cudaGetSymbolAddress(&paoh, g_aoh); cudaGetSymbolAddress(&paol, g_aol);
    cudaGetSymbolAddress(&pwqh, g_wqh); cudaGetSymbolAddress(&pwql, g_wql);
    cudaGetSymbolAddress(&pwkh, g_wkh); cudaGetSymbolAddress(&pwkl, g_wkl);
    cudaGetSymbolAddress(&pwvh, g_wvh); cudaGetSymbolAddress(&pwvl, g_wvl);
    cudaGetSymbolAddress(&pwoh, g_woh); cudaGetSymbolAddress(&pwol, g_wol);
    cudaGetSymbolAddress(&pqh, g_qh);  cudaGetSymbolAddress(&pql, g_ql);
    cudaGetSymbolAddress(&pkh, g_kh);  cudaGetSymbolAddress(&pkl, g_kl);
    cudaGetSymbolAddress(&pvh, g_vh);  cudaGetSymbolAddress(&pvl, g_vl);

    float* q  = (float*)pq;  float* k = (float*)pk;
    float* v  = (float*)pv;  float* ao = (float*)pao;
    __nv_bfloat16 *xh = (__nv_bfloat16*)pxh,  *xl = (__nv_bfloat16*)pxl;
    __nv_bfloat16 *aoh = (__nv_bfloat16*)paoh, *aol = (__nv_bfloat16*)paol;
    __nv_bfloat16 *wqh = (__nv_bfloat16*)pwqh, *wql = (__nv_bfloat16*)pwql;
    __nv_bfloat16 *wkh = (__nv_bfloat16*)pwkh, *wkl = (__nv_bfloat16*)pwkl;
    __nv_bfloat16 *wvh = (__nv_bfloat16*)pwvh, *wvl = (__nv_bfloat16*)pwvl;
    __nv_bfloat16 *woh = (__nv_bfloat16*)pwoh, *wol = (__nv_bfloat16*)pwol;
    __nv_bfloat16 *qhp = (__nv_bfloat16*)pqh,  *qlp = (__nv_bfloat16*)pql;
    __nv_bfloat16 *khp = (__nv_bfloat16*)pkh,  *klp = (__nv_bfloat16*)pkl;
    __nv_bfloat16 *vhp = (__nv_bfloat16*)pvh,  *vlp = (__nv_bfloat16*)pvl;

    // Splits: activations + weights
    {
        int n4 = MR * Ee / 4;
        split_bf16<<<(n4 + 255) / 256, 256>>>(x, xh, xl, n4, 1.f);
        int w4 = NH * HD * Ee / 4;
        split_bf16<<<(w4 + 255) / 256, 256>>>(Wq, wqh, wql, w4, 1.f);
        int k4 = NKV * HD * Ee / 4;
        split_bf16<<<(k4 + 255) / 256, 256>>>(Wk, wkh, wkl, k4, 1.f);
        split_bf16<<<(k4 + 255) / 256, 256>>>(Wv, wvh, wvl, k4, 1.f);
        int o4 = Ee * Ee / 4;
        split_bf16<<<(o4 + 255) / 256, 256>>>(Wo, woh, wol, o4, 1.f);
    }

    cudaFuncSetAttribute(gemm_mma, cudaFuncAttributeMaxDynamicSharedMemorySize, GSMEM);

    // QKV projections
    gemm_mma<<<dim3((NH * HD) / 128, MR / 128), 256, GSMEM>>>(xh, xl, wqh, wql, q, MR, NH * HD, Ee);
    gemm_mma<<<dim3((NKV * HD) / 128, MR / 128), 256, GSMEM>>>(xh, xl, wkh, wkl, k, MR, NKV * HD, Ee);
    gemm_mma<<<dim3((NKV * HD) / 128, MR / 128), 256, GSMEM>>>(xh, xl, wvh, wvl, v, MR, NKV * HD, Ee);

    // RoPE (fp32)
    {
        int tq = MR * NH * 64;
        rope_kernel<<<(tq + 255) / 256, 256>>>(q, cosT, sinT, NH, tq);
        int tk = MR * NKV * 64;
        rope_kernel<<<(tk + 255) / 256, 256>>>(k, cosT, sinT, NKV, tk);
    }

    // Split q (scale folded), k, v for the MMA flash kernel
    {
        const float scale = 0.08838834764831845f;  // 1/sqrt(128)
        int q4 = MR * NH * HD / 4;
        split_bf16<<<(q4 + 255) / 256, 256>>>(q, qhp, qlp, q4, scale);
        int kv4 = MR * NKV * HD / 4;
        split_bf16<<<(kv4 + 255) / 256, 256>>>(k, khp, klp, kv4, 1.f);
        split_bf16<<<(kv4 + 255) / 256, 256>>>(v, vhp, vlp, kv4, 1.f);
    }

    // HMMA windowed flash attention
    cudaFuncSetAttribute(flash_mma, cudaFuncAttributeMaxDynamicSharedMemorySize, FLASH_SMEM);
    flash_mma<<<dim3(Ss / 128, NH, Bb), 256, FLASH_SMEM>>>(qhp, qlp, khp, klp, vhp, vlp, ao);

    // Output projection
    {
        int n4 = MR * Ee / 4;
        split_bf16<<<(n4 + 255) / 256, 256>>>(ao, aoh, aol, n4, 1.f);
    }
    gemm_mma<<<dim3(Ee / 128, MR / 128), 256, GSMEM>>>(aoh, aol, woh, wol, out, MR, Ee, Ee);
}

// round 6
// speedup vs baseline: 3.8598x; 1.0998x over previous
#include <cuda_runtime.h>
#include <cuda_bf16.h>
#include <cstdint>
#include <math.h>

#define Bb 2
#define Ss 2048
#define Ee 2048
#define NH 16
#define NKV 4
#define HD 128
#define WIN 1024
#define GQ (NH / NKV)
#define MR (Bb * Ss)   // 4096 rows
#define NQKV (NH * HD + 2 * NKV * HD)  // 3072

// ---------------------------------------------------------------------------
// Scratch (device globals; no allocation allowed)
// ---------------------------------------------------------------------------
__device__ __nv_bfloat16 g_xh[(size_t)MR * Ee],  g_xl[(size_t)MR * Ee];
__device__ __nv_bfloat16 g_aoh[(size_t)MR * Ee], g_aol[(size_t)MR * Ee];
__device__ __nv_bfloat16 g_wqkvh[(size_t)NQKV * Ee], g_wqkvl[(size_t)NQKV * Ee];
__device__ __nv_bfloat16 g_woh[(size_t)Ee * Ee],  g_wol[(size_t)Ee * Ee];

__device__ __nv_bfloat16 g_qh[(size_t)MR * NH * HD],  g_ql[(size_t)MR * NH * HD];
__device__ __nv_bfloat16 g_kh[(size_t)MR * NKV * HD], g_kl[(size_t)MR * NKV * HD];
__device__ __nv_bfloat16 g_vh[(size_t)MR * NKV * HD], g_vl[(size_t)MR * NKV * HD];

// ---------------------------------------------------------------------------
// PTX helpers (baseline sm_80+ only — tcgen05 is rejected by compute_103)
// ---------------------------------------------------------------------------
static __device__ __forceinline__ uint32_t smem_u32(const void* p) {
    uint32_t a;
    asm("{ .reg .u64 t; cvta.to.shared.u64 t, %1; cvt.u32.u64 %0, t; }" : "=r"(a) : "l"(p));
    return a;
}
static __device__ __forceinline__ void ldsm4(uint32_t* r, uint32_t addr) {
    asm volatile("ldmatrix.sync.aligned.m8n8.x4.shared.b16 {%0,%1,%2,%3}, [%4];"
                 : "=r"(r[0]), "=r"(r[1]), "=r"(r[2]), "=r"(r[3]) : "r"(addr));
}
static __device__ __forceinline__ void ldsm4t(uint32_t* r, uint32_t addr) {
    asm volatile("ldmatrix.sync.aligned.m8n8.x4.trans.shared.b16 {%0,%1,%2,%3}, [%4];"
                 : "=r"(r[0]), "=r"(r[1]), "=r"(r[2]), "=r"(r[3]) : "r"(addr));
}
static __device__ __forceinline__ void mma16816(float* d, const uint32_t* a, const uint32_t* b) {
    asm volatile(
        "mma.sync.aligned.m16n8k16.row.col.f32.bf16.bf16.f32 "
        "{%0,%1,%2,%3}, {%4,%5,%6,%7}, {%8,%9}, {%0,%1,%2,%3};"
        : "+f"(d[0]), "+f"(d[1]), "+f"(d[2]), "+f"(d[3])
        : "r"(a[0]), "r"(a[1]), "r"(a[2]), "r"(a[3]), "r"(b[0]), "r"(b[1]));
}

#define CP_ASYNC16(sa, gp) \
    asm volatile("cp.async.cg.shared.global [%0], [%1], 16;" :: "r"(sa), "l"(gp))
#define CP_COMMIT()  asm volatile("cp.async.commit_group;" ::: "memory")
#define CP_WAIT0()   asm volatile("cp.async.wait_group 0;" ::: "memory")

// swizzled offset for (row r, 16B-chunk c) in a 64B-row subtile
static __device__ __forceinline__ uint32_t swoff(int r, int c) {
    return (uint32_t)(r * 64 + ((c ^ ((r >> 1) & 3)) << 4));
}

// pack two floats -> bf16x2 hi reg, lo reg via out-param
static __device__ __forceinline__ uint32_t packsplit(float a, float b, uint32_t& lo) {
    __nv_bfloat162 h = __floats2bfloat162_rn(a, b);
    float2 hf = __bfloat1622float2(h);
    __nv_bfloat162 l = __floats2bfloat162_rn(a - hf.x, b - hf.y);
    lo = *reinterpret_cast<uint32_t*>(&l);
    return *reinterpret_cast<uint32_t*>(&h);
}

// ---------------------------------------------------------------------------
// fp32 -> bf16 hi/lo split (x4)
// ---------------------------------------------------------------------------
__global__ void split_bf16(const float* __restrict__ in,
                           __nv_bfloat16* __restrict__ hi,
                           __nv_bfloat16* __restrict__ lo, int n4)
{
    int i = blockIdx.x * blockDim.x + threadIdx.x;
    if (i >= n4) return;
    float4 v = ((const float4*)in)[i];
    float vv[4] = {v.x, v.y, v.z, v.w};
    ushort4 hu, lu;
    unsigned short* hp = &hu.x;
    unsigned short* lp = &lu.x;
#pragma unroll
    for (int j = 0; j < 4; j++) {
        __nv_bfloat16 h = __float2bfloat16(vv[j]);
        __nv_bfloat16 l = __float2bfloat16(vv[j] - __bfloat162float(h));
        hp[j] = __bfloat16_as_ushort(h);
        lp[j] = __bfloat16_as_ushort(l);
    }
    ((ushort4*)hi)[i] = hu;
    ((ushort4*)lo)[i] = lu;
}

// ---------------------------------------------------------------------------
// Shared GEMM mainloop pieces
// ---------------------------------------------------------------------------
#define GSTAGE 32768
#define GSMEM  (2 * GSTAGE)

static __device__ __forceinline__ void ld_tile32(
    uint32_t sdst, const __nv_bfloat16* gsrc, int K, int kt, int t)
{
#pragma unroll
    for (int i = 0; i < 2; i++) {
        int ci = t + i * 256;
        int r = ci >> 2, c = ci & 3;
        const char* gp = (const char*)(gsrc + (size_t)r * K + kt * 32 + c * 8);
        CP_ASYNC16(sdst + swoff(r, c), gp);
    }
}

// Mainloop computing a 128x128 fp32 tile in acc[2][8][4]
static __device__ __forceinline__ void gemm_mainloop(
    uint32_t sb, const __nv_bfloat16* Ahb, const __nv_bfloat16* Alb,
    const __nv_bfloat16* Bhb, const __nv_bfloat16* Blb, int K, int t,
    float acc[2][8][4])
{
    const int lane = t & 31;
    const int wid  = t >> 5;
    const int wm   = (wid & 3) * 32;
    const int wn   = (wid >> 2) * 64;
    const int nchunk = K / 32;

    ld_tile32(sb + 0,     Ahb, K, 0, t);
    ld_tile32(sb + 8192,  Alb, K, 0, t);
    ld_tile32(sb + 16384, Bhb, K, 0, t);
    ld_tile32(sb + 24576, Blb, K, 0, t);
    CP_COMMIT();

    const int a_row  = lane & 15;
    const int a_cofs = lane >> 4;
    const int b_row  = (lane & 7) + ((lane & 16) ? 8 : 0);
    const int b_cofs = (lane >> 3) & 1;

    for (int kt = 0; kt < nchunk; kt++) {
        CP_WAIT0();
        __syncthreads();
        if (kt + 1 < nchunk) {
            const uint32_t sn = sb + (uint32_t)((kt + 1) & 1) * GSTAGE;
            ld_tile32(sn + 0,     Ahb, K, kt + 1, t);
            ld_tile32(sn + 8192,  Alb, K, kt + 1, t);
            ld_tile32(sn + 16384, Bhb, K, kt + 1, t);
            ld_tile32(sn + 24576, Blb, K, kt + 1, t);
            CP_COMMIT();
        }
        const uint32_t so = sb + (uint32_t)(kt & 1) * GSTAGE;

#pragma unroll
        for (int ks = 0; ks < 2; ks++) {
            const int c = ks * 2;
            uint32_t ah[2][4], al[2][4];
#pragma unroll
            for (int mt = 0; mt < 2; mt++) {
                int r = wm + mt * 16 + a_row;
                ldsm4(ah[mt], so + 0    + swoff(r, c + a_cofs));
                ldsm4(al[mt], so + 8192 + swoff(r, c + a_cofs));
            }
#pragma unroll
            for (int pt = 0; pt < 4; pt++) {
                int r = wn + pt * 16 + b_row;
                uint32_t bh[4], bl[4];
                ldsm4(bh, so + 16384 + swoff(r, c + b_cofs));
                ldsm4(bl, so + 24576 + swoff(r, c + b_cofs));
#pragma unroll
                for (int mt = 0; mt < 2; mt++) {
#pragma unroll
                    for (int sub = 0; sub < 2; sub++) {
                        float* d = acc[mt][pt * 2 + sub];
                        mma16816(d, ah[mt], bh + sub * 2);
                        mma16816(d, ah[mt], bl + sub * 2);
                        mma16816(d, al[mt], bh + sub * 2);
                    }
                }
            }
        }
        __syncthreads();
    }
}

// ---------------------------------------------------------------------------
// Plain GEMM (fp32 output) — used for the output projection
// ---------------------------------------------------------------------------
__global__ void __launch_bounds__(256) gemm_mma(
    const __nv_bfloat16* __restrict__ Ah, const __nv_bfloat16* __restrict__ Al,
    const __nv_bfloat16* __restrict__ Bh, const __nv_bfloat16* __restrict__ Bl,
    float* __restrict__ C, int M, int N, int K)
{
    extern __shared__ char rawsm[];
    const uint32_t sb = smem_u32(rawsm);
    const int t    = threadIdx.x;
    const int lane = t & 31;
    const int wid  = t >> 5;
    const int wm   = (wid & 3) * 32;
    const int wn   = (wid >> 2) * 64;
    const int bm = blockIdx.y, bn = blockIdx.x;

    float acc[2][8][4];
#pragma unroll
    for (int i = 0; i < 2; i++)
#pragma unroll
        for (int j = 0; j < 8; j++)
#pragma unroll
            for (int r = 0; r < 4; r++) acc[i][j][r] = 0.f;

    gemm_mainloop(sb, Ah + (size_t)bm * 128 * K, Al + (size_t)bm * 128 * K,
                  Bh + (size_t)bn * 128 * K, Bl + (size_t)bn * 128 * K, K, t, acc);

    const int gr = lane >> 2, tg = lane & 3;
#pragma unroll
    for (int mt = 0; mt < 2; mt++) {
#pragma unroll
        for (int nt = 0; nt < 8; nt++) {
            int row0 = bm * 128 + wm + mt * 16 + gr;
            int col  = bn * 128 + wn + nt * 8 + tg * 2;
            float* d = acc[mt][nt];
            *(float2*)(C + (size_t)row0 * N + col)       = make_float2(d[0], d[1]);
            *(float2*)(C + (size_t)(row0 + 8) * N + col) = make_float2(d[2], d[3]);
        }
    }
}

// ---------------------------------------------------------------------------
// Fused QKV GEMM: N=3072 tiles; epilogue applies RoPE (q,k), scale (q),
// hi/lo split, writes bf16 directly. Each N-tile of 128 = exactly one head.
// bn 0..15 -> q head bn | bn 16..19 -> k head bn-16 | bn 20..23 -> v head bn-20
// ---------------------------------------------------------------------------
__global__ void __launch_bounds__(256) gemm_qkv(
    const __nv_bfloat16* __restrict__ Ah, const __nv_bfloat16* __restrict__ Al,
    const __nv_bfloat16* __restrict__ Bh, const __nv_bfloat16* __restrict__ Bl,
    const float* __restrict__ cosT, const float* __restrict__ sinT,
    __nv_bfloat16* __restrict__ qh, __nv_bfloat16* __restrict__ ql,
    __nv_bfloat16* __restrict__ kh, __nv_bfloat16* __restrict__ kl,
    __nv_bfloat16* __restrict__ vh, __nv_bfloat16* __restrict__ vl)
{
    extern __shared__ char rawsm[];
    const uint32_t sb = smem_u32(rawsm);
    const int t    = threadIdx.x;
    const int lane = t & 31;
    const int wid  = t >> 5;
    const int wm   = (wid & 3) * 32;
    const int wn   = (wid >> 2) * 64;
    const int bm = blockIdx.y, bn = blockIdx.x;
    const int K = Ee;

    float acc[2][8][4];
#pragma unroll
    for (int i = 0; i < 2; i++)
#pragma unroll
        for (int j = 0; j < 8; j++)
#pragma unroll
            for (int r = 0; r < 4; r++) acc[i][j][r] = 0.f;

    gemm_mainloop(sb, Ah + (size_t)bm * 128 * K, Al + (size_t)bm * 128 * K,
                  Bh + (size_t)bn * 128 * K, Bl + (size_t)bn * 128 * K, K, t, acc);

    // epilogue routing
    __nv_bfloat16 *dh, *dl;
    int nheads, hsel;
    bool dorope;
    float sc;
    if (bn < 16)      { dh = qh; dl = ql; nheads = NH;  hsel = bn;      dorope = true;  sc = 0.08838834764831845f; }
    else if (bn < 20) { dh = kh; dl = kl; nheads = NKV; hsel = bn - 16; dorope = true;  sc = 1.f; }
    else              { dh = vh; dl = vl; nheads = NKV; hsel = bn - 20; dorope = false; sc = 1.f; }

    float* es = (float*)rawsm;   // 64 x 132 staging
    const int gr = lane >> 2, tg = lane & 3;

#pragma unroll
    for (int half = 0; half < 2; half++) {
        const int h0 = half * 64;
        __syncthreads();
        // stage fragments whose rows fall in [h0, h0+64)
        if ((wm & 64) == h0) {
#pragma unroll
            for (int mt = 0; mt < 2; mt++) {
                int r0 = (wm & 32) + mt * 16 + gr;
#pragma unroll
                for (int nt = 0; nt < 8; nt++) {
                    int col = wn + nt * 8 + tg * 2;
                    float* d = acc[mt][nt];
                    *(float2*)(es + r0 * 132 + col)       = make_float2(d[0], d[1]);
                    *(float2*)(es + (r0 + 8) * 132 + col) = make_float2(d[2], d[3]);
                }
            }
        }
        __syncthreads();
        // rope + split + store: 64 rows x 32 even-d groups = 2048 quads
#pragma unroll
        for (int i = 0; i < 8; i++) {
            int p = t + i * 256;
            int r = p >> 5;
            int dd = (p & 31) * 2;
            int grow = bm * 128 + h0 + r;
            int s = grow & (Ss - 1);
            float2 xa = *(const float2*)(es + r * 132 + dd);
            float2 xb = *(const float2*)(es + r * 132 + dd + 64);
            float o1a, o1b, o2a, o2b;
            if (dorope) {
                float2 c1 = *(const float2*)(cosT + (size_t)s * HD + dd);
                float2 s1 = *(const float2*)(sinT + (size_t)s * HD + dd);
                float2 c2 = *(const float2*)(cosT + (size_t)s * HD + dd + 64);
                float2 s2 = *(const float2*)(sinT + (size_t)s * HD + dd + 64);
                o1a = xa.x * c1.x - xb.x * s1.x;
                o1b = xa.y * c1.y - xb.y * s1.y;
                o2a = xb.x * c2.x + xa.x * s2.x;
                o2b = xb.y * c2.y + xa.y * s2.y;
            } else {
                o1a = xa.x; o1b = xa.y; o2a = xb.x; o2b = xb.y;
            }
            o1a *= sc; o1b *= sc; o2a *= sc; o2b *= sc;
            size_t base = ((size_t)grow * nheads + hsel) * HD;
            uint32_t lo1, lo2;
            uint32_t hi1 = packsplit(o1a, o1b, lo1);
            uint32_t hi2 = packsplit(o2a, o2b, lo2);
            *(uint32_t*)(dh + base + dd)      = hi1;
            *(uint32_t*)(dl + base + dd)      = lo1;
            *(uint32_t*)(dh + base + dd + 64) = hi2;
            *(uint32_t*)(dl + base + dd + 64) = lo2;
        }
    }
}

// ---------------------------------------------------------------------------
// HMMA windowed-causal flash attention (fp32-equivalent via bf16 hi/lo split)
// CTA: 128 q-rows x one head x one batch. 8 warps x 16 rows. j-tile = 64 keys.
// Epilogue writes hi/lo bf16 of O directly.
// ---------------------------------------------------------------------------
#define FQH  0
#define FQL  32768
#define FST  65536
#define FSTG 65536
#define FLASH_SMEM (FST + 2 * FSTG)   // 196608

static __device__ __forceinline__ void flash_ld_q(
    uint32_t sq, const __nv_bfloat16* gq, int bs0, int h, int t)
{
#pragma unroll
    for (int i = 0; i < 8; i++) {
        int id = t + i * 256;
        int sub = id >> 9, rem = id & 511;
        int r = rem >> 2, c = rem & 3;
        const char* gp = (const char*)(gq + ((size_t)(bs0 + r) * NH + h) * HD + sub * 32 + c * 8);
        CP_ASYNC16(sq + sub * 8192 + swoff(r, c), gp);
    }
}
static __device__ __forceinline__ void flash_ld_kv(
    uint32_t sdst, const __nv_bfloat16* gsrc, int bs0, int hk, int t)
{
#pragma unroll
    for (int i = 0; i < 4; i++) {
        int id = t + i * 256;
        int sub = id >> 8, rem = id & 255;
        int r = rem >> 2, c = rem & 3;
        const char* gp = (const char*)(gsrc + ((size_t)(bs0 + r) * NKV + hk) * HD + sub * 32 + c * 8);
        CP_ASYNC16(sdst + sub * 4096 + swoff(r, c), gp);
    }
}

__global__ void __launch_bounds__(256) flash_mma(
    const __nv_bfloat16* __restrict__ qh, const __nv_bfloat16* __restrict__ ql,
    const __nv_bfloat16* __restrict__ kh, const __nv_bfloat16* __restrict__ kl,
    const __nv_bfloat16* __restrict__ vh, const __nv_bfloat16* __restrict__ vl,
    __nv_bfloat16* __restrict__ aoh, __nv_bfloat16* __restrict__ aol)
{
    extern __shared__ char rawsm[];
    const uint32_t sb = smem_u32(rawsm);

    const int t    = threadIdx.x;
    const int lane = t & 31;
    const int wid  = t >> 5;
    const int wm   = wid * 16;
    const int qt = blockIdx.x, h = blockIdx.y, b = blockIdx.z;
    const int hk = h / GQ;
    const int q0 = qt * 128;
    const int bs = b * Ss;

    const int a_row  = lane & 15;
    const int a_cofs = lane >> 4;
    const int b_row  = (lane & 7) + ((lane & 16) ? 8 : 0);
    const int b_cofs = (lane >> 3) & 1;
    const int v_row  = lane & 15;
    const int v_cofs = lane >> 4;

    float m0 = -1e30f, m1 = -1e30f, l0 = 0.f, l1 = 0.f;
    float o[16][4];
#pragma unroll
    for (int j = 0; j < 16; j++)
#pragma unroll
        for (int r = 0; r < 4; r++) o[j][r] = 0.f;

    int lo = q0 - (WIN - 1); if (lo < 0) lo = 0;
    const int jt0 = lo >> 6;
    const int jt1 = (q0 + 127) >> 6;

    flash_ld_q(sb + FQH, qh, bs + q0, h, t);
    flash_ld_q(sb + FQL, ql, bs + q0, h, t);
    {
        const uint32_t s0 = sb + FST + (uint32_t)(jt0 & 1) * FSTG;
        flash_ld_kv(s0 + 0,     kh, bs + jt0 * 64, hk, t);
        flash_ld_kv(s0 + 16384, kl, bs + jt0 * 64, hk, t);
        flash_ld_kv(s0 + 32768, vh, bs + jt0 * 64, hk, t);
        flash_ld_kv(s0 + 49152, vl, bs + jt0 * 64, hk, t);
    }
    CP_COMMIT();

    const int gi0 = q0 + wm + (lane >> 2);
    const int gi1 = gi0 + 8;
    const int colq = (lane & 3) * 2;

    for (int jt = jt0; jt <= jt1; jt++) {
        const int j0 = jt * 64;
        CP_WAIT0();
        __syncthreads();
        if (jt + 1 <= jt1) {
            const uint32_t sn = sb + FST + (uint32_t)((jt + 1) & 1) * FSTG;
            flash_ld_kv(sn + 0,     kh, bs + (jt + 1) * 64, hk, t);
            flash_ld_kv(sn + 16384, kl, bs + (jt + 1) * 64, hk, t);
            flash_ld_kv(sn + 32768, vh, bs + (jt + 1) * 64, hk, t);
            flash_ld_kv(sn + 49152, vl, bs + (jt + 1) * 64, hk, t);
            CP_COMMIT();
        }
        const uint32_t st = sb + FST + (uint32_t)(jt & 1) * FSTG;

        float s[8][4];
#pragma unroll
        for (int j = 0; j < 8; j++)
#pragma unroll
            for (int r = 0; r < 4; r++) s[j][r] = 0.f;

#pragma unroll
        for (int kc = 0; kc < 8; kc++) {
            const int sub = kc >> 1, cb = (kc & 1) * 2;
            uint32_t ah[4], al[4];
            uint32_t qa = sb + FQH + sub * 8192 + swoff(wm + a_row, cb + a_cofs);
            ldsm4(ah, qa);
            ldsm4(al, qa + 32768);
#pragma unroll
            for (int nt = 0; nt < 4; nt++) {
                uint32_t ka = st + sub * 4096 + swoff(nt * 16 + b_row, cb + b_cofs);
                uint32_t bh[4], bl[4];
                ldsm4(bh, ka);
                ldsm4(bl, ka + 16384);
#pragma unroll
                for (int su = 0; su < 2; su++) {
                    float* d = s[nt * 2 + su];
                    mma16816(d, ah, bh + su * 2);
                    mma16816(d, ah, bl + su * 2);
                    mma16816(d, al, bh + su * 2);
                }
            }
        }

        float mt0 = -1e30f, mt1 = -1e30f;
#pragma unroll
        for (int j = 0; j < 8; j++) {
            int c0 = j0 + j * 8 + colq;
#pragma unroll
            for (int e = 0; e < 2; e++) {
                int cc = c0 + e;
                int d0 = gi0 - cc, d1 = gi1 - cc;
                if (d0 < 0 || d0 >= WIN) s[j][e] = -1e30f;
                if (d1 < 0 || d1 >= WIN) s[j][2 + e] = -1e30f;
                mt0 = fmaxf(mt0, s[j][e]);
                mt1 = fmaxf(mt1, s[j][2 + e]);
            }
        }
#pragma unroll
        for (int off = 1; off <= 2; off <<= 1) {
            mt0 = fmaxf(mt0, __shfl_xor_sync(0xffffffffu, mt0, off));
            mt1 = fmaxf(mt1, __shfl_xor_sync(0xffffffffu, mt1, off));
        }
        float mn0 = fmaxf(m0, mt0), mn1 = fmaxf(m1, mt1);
        float al0 = __expf(m0 - mn0), al1 = __expf(m1 - mn1);
        m0 = mn0; m1 = mn1;

        float rs0 = 0.f, rs1 = 0.f;
#pragma unroll
        for (int j = 0; j < 8; j++) {
#pragma unroll
            for (int e = 0; e < 2; e++) {
                float p0 = (s[j][e]     > -1e29f) ? __expf(s[j][e]     - mn0) : 0.f;
                float p1 = (s[j][2 + e] > -1e29f) ? __expf(s[j][2 + e] - mn1) : 0.f;
                s[j][e] = p0; s[j][2 + e] = p1;
                rs0 += p0; rs1 += p1;
            }
        }
#pragma unroll
        for (int off = 1; off <= 2; off <<= 1) {
            rs0 += __shfl_xor_sync(0xffffffffu, rs0, off);
            rs1 += __shfl_xor_sync(0xffffffffu, rs1, off);
        }
        l0 = l0 * al0 + rs0;
        l1 = l1 * al1 + rs1;
#pragma unroll
        for (int j = 0; j < 16; j++) {
            o[j][0] *= al0; o[j][1] *= al0;
            o[j][2] *= al1; o[j][3] *= al1;
        }

#pragma unroll
        for (int kc2 = 0; kc2 < 4; kc2++) {
            uint32_t phi[4], plo[4];
            phi[0] = packsplit(s[2 * kc2][0],     s[2 * kc2][1],     plo[0]);
            phi[1] = packsplit(s[2 * kc2][2],     s[2 * kc2][3],     plo[1]);
            phi[2] = packsplit(s[2 * kc2 + 1][0], s[2 * kc2 + 1][1], plo[2]);
            phi[3] = packsplit(s[2 * kc2 + 1][2], s[2 * kc2 + 1][3], plo[3]);
#pragma unroll
            for (int nt = 0; nt < 8; nt++) {
                const int sub = nt >> 1, cb = (nt & 1) * 2;
                uint32_t va = st + 32768 + sub * 4096
                            + swoff(kc2 * 16 + v_row, cb + v_cofs);
                uint32_t vhf[4], vlf[4];
                ldsm4t(vhf, va);
                ldsm4t(vlf, va + 16384);
#pragma unroll
                for (int su = 0; su < 2; su++) {
                    float* d = o[nt * 2 + su];
                    mma16816(d, phi, vhf + su * 2);
                    mma16816(d, phi, vlf + su * 2);
                    mma16816(d, plo, vhf + su * 2);
                }
            }
        }
    }

    // epilogue: normalize + split + write bf16 hi/lo
    float inv0 = 1.f / l0, inv1 = 1.f / l1;
#pragma unroll
    for (int j = 0; j < 16; j++) {
        int col = j * 8 + colq;
        size_t b0 = ((size_t)(bs + gi0) * NH + h) * HD + col;
        size_t b1 = ((size_t)(bs + gi1) * NH + h) * HD + col;
        uint32_t lo0, lo1v;
        uint32_t hi0 = packsplit(o[j][0] * inv0, o[j][1] * inv0, lo0);
        uint32_t hi1 = packsplit(o[j][2] * inv1, o[j][3] * inv1, lo1v);
        *(uint32_t*)(aoh + b0) = hi0;
        *(uint32_t*)(aol + b0) = lo0;
        *(uint32_t*)(aoh + b1) = hi1;
        *(uint32_t*)(aol + b1) = lo1v;
    }
}

// ---------------------------------------------------------------------------
extern "C" void kernel_launch(void* const* d_in, const int* in_sizes, int n_in,
                              void* d_out, int out_size)
{
    const float* x    = (const float*)d_in[0];
    const float* cosT = (const float*)d_in[1];
    const float* sinT = (const float*)d_in[2];
    const float* Wq   = (const float*)d_in[3];
    const float* Wk   = (const float*)d_in[4];
    const float* Wv   = (const float*)d_in[5];
    const float* Wo   = (const float*)d_in[6];
    float* out = (float*)d_out;

    void *pxh, *pxl, *paoh, *paol, *pwh, *pwl, *pwoh, *pwol;
    void *pqh, *pql, *pkh, *pkl, *pvh, *pvl;
    cudaGetSymbolAddress(&pxh, g_xh);   cudaGetSymbolAddress(&pxl, g_xl);
    cudaGetSymbolAddress(&paoh, g_aoh); cudaGetSymbolAddress(&paol, g_aol);
    cudaGetSymbolAddress(&pwh, g_wqkvh); cudaGetSymbolAddress(&pwl, g_wqkvl);
    cudaGetSymbolAddress(&pwoh, g_woh); cudaGetSymbolAddress(&pwol, g_wol);
    cudaGetSymbolAddress(&pqh, g_qh);  cudaGetSymbolAddress(&pql, g_ql);
    cudaGetSymbolAddress(&pkh, g_kh);  cudaGetSymbolAddress(&pkl, g_kl);
    cudaGetSymbolAddress(&pvh, g_vh);  cudaGetSymbolAddress(&pvl, g_vl);

    __nv_bfloat16 *xh = (__nv_bfloat16*)pxh,   *xl = (__nv_bfloat16*)pxl;
    __nv_bfloat16 *aoh = (__nv_bfloat16*)paoh, *aol = (__nv_bfloat16*)paol;
    __nv_bfloat16 *wh = (__nv_bfloat16*)pwh,   *wl = (__nv_bfloat16*)pwl;
    __nv_bfloat16 *woh = (__nv_bfloat16*)pwoh, *wol = (__nv_bfloat16*)pwol;
    __nv_bfloat16 *qhp = (__nv_bfloat16*)pqh,  *qlp = (__nv_bfloat16*)pql;
    __nv_bfloat16 *khp = (__nv_bfloat16*)pkh,  *klp = (__nv_bfloat16*)pkl;
    __nv_bfloat16 *vhp = (__nv_bfloat16*)pvh,  *vlp = (__nv_bfloat16*)pvl;

    // Splits: x, fused wqkv (Wq | Wk | Wv rows), wo
    {
        int n4 = MR * Ee / 4;
        split_bf16<<<(n4 + 255) / 256, 256>>>(x, xh, xl, n4);
        int w4 = NH * HD * Ee / 4;
        split_bf16<<<(w4 + 255) / 256, 256>>>(Wq, wh, wl, w4);
        int k4 = NKV * HD * Ee / 4;
        size_t koff = (size_t)NH * HD * Ee;
        size_t voff = koff + (size_t)NKV * HD * Ee;
        split_bf16<<<(k4 + 255) / 256, 256>>>(Wk, wh + koff, wl + koff, k4);
        split_bf16<<<(k4 + 255) / 256, 256>>>(Wv, wh + voff, wl + voff, k4);
        int o4 = Ee * Ee / 4;
        split_bf16<<<(o4 + 255) / 256, 256>>>(Wo, woh, wol, o4);
    }

    cudaFuncSetAttribute(gemm_qkv, cudaFuncAttributeMaxDynamicSharedMemorySize, GSMEM);
    cudaFuncSetAttribute(gemm_mma, cudaFuncAttributeMaxDynamicSharedMemorySize, GSMEM);

    // Fused QKV projection + RoPE + split epilogue
    gemm_qkv<<<dim3(NQKV / 128, MR / 128), 256, GSMEM>>>(
        xh, xl, wh, wl, cosT, sinT, qhp, qlp, khp, klp, vhp, vlp);

    // HMMA windowed flash attention (writes aoh/aol)
    cudaFuncSetAttribute(flash_mma, cudaFuncAttributeMaxDynamicSharedMemorySize, FLASH_SMEM);
    flash_mma<<<dim3(Ss / 128, NH, Bb), 256, FLASH_SMEM>>>(
        qhp, qlp, khp, klp, vhp, vlp, aoh, aol);

    // Output projection
    gemm_mma<<<dim3(Ee / 128, MR / 128), 256, GSMEM>>>(aoh, aol, woh, wol, out, MR, Ee, Ee);
}